// round 6
// baseline (speedup 1.0000x reference)
#include <cuda_runtime.h>
#include <cstdint>

#define N_MAX   100000
#define E_MAX   1600000
#define EL_MAX  6400000

// ---------------- scratch (device globals; no dynamic allocation) ----------------
__device__ float g_ze1[E_MAX * 16];
__device__ float g_ze2[E_MAX * 16];
__device__ float g_zet[E_MAX * 16];
__device__ float g_ze4[E_MAX * 16];
__device__ float g_xyagg[E_MAX * 16];
__device__ float g_zn1[N_MAX * 16];
__device__ float g_zn2[N_MAX * 16];
__device__ float g_znt[N_MAX * 16];
__device__ float g_zn4[N_MAX * 16];
__device__ float g_yx[N_MAX * 16];

__device__ int g_tmp_lg[E_MAX];        // counts, then cursors
__device__ int g_off_lg[E_MAX + 1];
__device__ int g_csr_lg_src[EL_MAX];
__device__ int g_csr_lg_dst[EL_MAX];
__device__ int g_csr_lg_b[EL_MAX];     // e2n[src] pre-gathered
__device__ int g_tmp_g[N_MAX];
__device__ int g_off_g[N_MAX + 1];
__device__ int g_csr_g_src[E_MAX];
__device__ int g_csr_g_dst[E_MAX];
__device__ int g_csr_g_b[E_MAX];       // edge id
__device__ int g_bsums_lg[2048];
__device__ int g_bsums_g[256];

__device__ int g_zlist_lg[E_MAX + EL_MAX / 64 + 64];
__device__ int g_zlist_g[N_MAX + E_MAX / 64 + 64];
__device__ int g_zcnt[2];

__device__ float g_stats[64];
__device__ float g_bn[64];

#define RED4(p, v)                                                              \
    asm volatile("red.global.add.v4.f32 [%0], {%1, %2, %3, %4};"                \
                 :: "l"(p), "f"((v).x), "f"((v).y), "f"((v).z), "f"((v).w)      \
                 : "memory")

static inline unsigned cdiv_u(long long a, long long b) { return (unsigned)((a + b - 1) / b); }

// ---------------- f32x2 helpers ----------------
__device__ __forceinline__ unsigned long long pk2(float a, float b) {
    unsigned long long r;
    asm("mov.b64 %0, {%1, %2};" : "=l"(r) : "r"(__float_as_uint(a)), "r"(__float_as_uint(b)));
    return r;
}
__device__ __forceinline__ unsigned long long fma2(
    unsigned long long a, unsigned long long b, unsigned long long c) {
    unsigned long long d;
    asm("fma.rn.f32x2 %0, %1, %2, %3;" : "=l"(d) : "l"(a), "l"(b), "l"(c));
    return d;
}
__device__ __forceinline__ void up2(unsigned long long v, float& lo, float& hi) {
    unsigned int a, b;
    asm("mov.b64 {%0, %1}, %2;" : "=r"(a), "=r"(b) : "l"(v));
    lo = __uint_as_float(a); hi = __uint_as_float(b);
}

// ---------------- small zero-init (counts + stats only) ----------------
__global__ void zero_small(int nE, int nN) {
    int i = blockIdx.x * blockDim.x + threadIdx.x;
    if (i < nE) g_tmp_lg[i] = 0;
    if (i < nN) g_tmp_g[i] = 0;
    if (i < 64) g_stats[i] = 0.f;
    if (i < 2)  g_zcnt[i] = 0;
}

// ---------------- CSR build ----------------
__global__ void __launch_bounds__(256) hist_k(const int* __restrict__ dst, int* __restrict__ cnt, int n) {
    int e = blockIdx.x * blockDim.x + threadIdx.x;
    if (e < n) atomicAdd(cnt + __ldg(dst + e), 1);
}

__global__ void __launch_bounds__(256) scan_blocks(
    const int* __restrict__ cnt, int* __restrict__ off, int* __restrict__ bsums, int n)
{
    __shared__ int warpsum[8];
    int t = threadIdx.x;
    int i0 = blockIdx.x * 1024 + t * 4;
    int4 v = make_int4(0, 0, 0, 0);
    if (i0 + 3 < n) v = *(const int4*)(cnt + i0);
    else {
        if (i0 < n)     v.x = cnt[i0];
        if (i0 + 1 < n) v.y = cnt[i0 + 1];
        if (i0 + 2 < n) v.z = cnt[i0 + 2];
    }
    int s = v.x + v.y + v.z + v.w;
    int lane = t & 31, w = t >> 5;
    int incl = s;
    #pragma unroll
    for (int o = 1; o < 32; o <<= 1) {
        int nv = __shfl_up_sync(0xFFFFFFFFu, incl, o);
        if (lane >= o) incl += nv;
    }
    if (lane == 31) warpsum[w] = incl;
    __syncthreads();
    if (t < 8) {
        int ws = warpsum[t];
        int in2 = ws;
        #pragma unroll
        for (int o = 1; o < 8; o <<= 1) {
            int nv = __shfl_up_sync(0x000000FFu, in2, o);
            if (t >= o) in2 += nv;
        }
        warpsum[t] = in2 - ws;  // exclusive
    }
    __syncthreads();
    int excl = warpsum[w] + incl - s;
    if (i0 < n) {
        int a = excl;
        off[i0] = a; a += v.x;
        if (i0 + 1 < n) off[i0 + 1] = a; a += v.y;
        if (i0 + 2 < n) off[i0 + 2] = a; a += v.z;
        if (i0 + 3 < n) off[i0 + 3] = a;
    }
    if (t == 255) bsums[blockIdx.x] = excl + s;  // block total
}

__global__ void __launch_bounds__(1024) scan_bsums(int* __restrict__ bsums, int nb) {
    __shared__ int wsum[32];
    int t = threadIdx.x;
    int k = (nb + 1023) >> 10;
    int i0 = t * k;
    int s = 0;
    for (int q = 0; q < k; q++) { int i = i0 + q; if (i < nb) s += bsums[i]; }
    int lane = t & 31, w = t >> 5;
    int incl = s;
    #pragma unroll
    for (int o = 1; o < 32; o <<= 1) {
        int nv = __shfl_up_sync(0xFFFFFFFFu, incl, o);
        if (lane >= o) incl += nv;
    }
    if (lane == 31) wsum[w] = incl;
    __syncthreads();
    if (t < 32) {
        int ws = wsum[t];
        int in2 = ws;
        #pragma unroll
        for (int o = 1; o < 32; o <<= 1) {
            int nv = __shfl_up_sync(0xFFFFFFFFu, in2, o);
            if (t >= o) in2 += nv;
        }
        wsum[t] = in2 - ws;
    }
    __syncthreads();
    int excl = wsum[w] + incl - s;
    for (int q = 0; q < k; q++) {
        int i = i0 + q;
        if (i < nb) { int v = bsums[i]; bsums[i] = excl; excl += v; }
    }
}

__global__ void __launch_bounds__(256) add_offsets(
    int* __restrict__ off, int* __restrict__ cur, const int* __restrict__ bsums,
    int n, int total)
{
    int i = blockIdx.x * 256 + threadIdx.x;
    if (i < n) {
        int v = off[i] + __ldg(bsums + (i >> 10));
        off[i] = v;
        cur[i] = v;
    }
    if (i == 0) off[n] = total;
}

// scatter with dst + secondary index columns
__global__ void __launch_bounds__(256) scatter_lg_k(
    const int* __restrict__ src, const int* __restrict__ dst,
    const int* __restrict__ e2n, int* __restrict__ cur,
    int* __restrict__ csrs, int* __restrict__ csrd, int* __restrict__ csrb, int n)
{
    int e = blockIdx.x * blockDim.x + threadIdx.x;
    if (e >= n) return;
    int s = __ldg(src + e);
    int d = __ldg(dst + e);
    int p = atomicAdd(cur + d, 1);
    csrs[p] = s;
    csrd[p] = d;
    csrb[p] = __ldg(e2n + s);
}

__global__ void __launch_bounds__(256) scatter_g_k(
    const int* __restrict__ src, const int* __restrict__ dst,
    int* __restrict__ cur,
    int* __restrict__ csrs, int* __restrict__ csrd, int* __restrict__ csrb, int n)
{
    int e = blockIdx.x * blockDim.x + threadIdx.x;
    if (e >= n) return;
    int d = __ldg(dst + e);
    int p = atomicAdd(cur + d, 1);
    csrs[p] = __ldg(src + e);
    csrd[p] = d;
    csrb[p] = e;
}

// rows needing pre-zero: block-boundary-spanning rows + empty rows
__global__ void __launch_bounds__(256) build_zero_list(
    const int* __restrict__ csr_dst, const int* __restrict__ off,
    int nrows, int nedges, int* __restrict__ list, int* __restrict__ cnt)
{
    int i = blockIdx.x * 256 + threadIdx.x;
    int nb = (nedges + 63) >> 6;
    if (i >= 1 && i < nb) {
        int p = i << 6;
        int d = __ldg(csr_dst + p);
        if (__ldg(csr_dst + p - 1) == d)
            list[atomicAdd(cnt, 1)] = d;
    }
    if (i < nrows && __ldg(off + i) == __ldg(off + i + 1))
        list[atomicAdd(cnt, 1)] = i;
}

__global__ void __launch_bounds__(256) prezero5(
    const int* __restrict__ list, const int* __restrict__ cnt,
    float* __restrict__ b0, float* __restrict__ b1, float* __restrict__ b2,
    float* __restrict__ b3, float* __restrict__ b4)
{
    int n = __ldg(cnt) * 4;
    int i = blockIdx.x * 256 + threadIdx.x;
    if (i >= n) return;
    int r = __ldg(list + (i >> 2));
    int c = i & 3;
    size_t idx = (size_t)r * 4 + c;
    float4 z = make_float4(0.f, 0.f, 0.f, 0.f);
    ((float4*)b0)[idx] = z;
    ((float4*)b1)[idx] = z;
    ((float4*)b2)[idx] = z;
    ((float4*)b3)[idx] = z;
    ((float4*)b4)[idx] = z;
}

// ---------------- edge-balanced segmented SpMM ----------------
// Block handles 64 consecutive CSR positions; thread = (edge slot, chunk).
// Phase 1: perfectly coalesced/balanced loads into smem.
// Phase 2: LOCAL segment heads (ke==0 is always a head) sum their run from
// smem; plain store for rows fully inside the block, red.global.add for rows
// spanning block boundaries (those rows are pre-zeroed).
__global__ void __launch_bounds__(256) spmm_seg(
    const float* __restrict__ z, const int* __restrict__ csr_src,
    const int* __restrict__ csr_dst, float* __restrict__ out, int nedges)
{
    __shared__ float sval[64 * 16];
    __shared__ int sdst[66];
    int K0 = blockIdx.x * 64;
    int t = threadIdx.x;
    int ke = t >> 2, c = t & 3;
    int k = K0 + ke;
    if (t < 66) {
        int kk = K0 - 1 + t;
        sdst[t] = (kk >= 0 && kk < nedges) ? __ldg(csr_dst + kk) : -1;
    }
    float4 v = make_float4(0.f, 0.f, 0.f, 0.f);
    if (k < nedges) {
        int s = __ldg(csr_src + k);
        v = __ldg((const float4*)z + (size_t)s * 4 + c);
    }
    ((float4*)sval)[ke * 4 + c] = v;
    __syncthreads();
    if (k >= nedges) return;
    int d = sdst[1 + ke];
    if (ke != 0 && sdst[ke] == d) return;  // not a local segment head
    int end = ke + 1;
    while (end < 64 && sdst[1 + end] == d) end++;
    float4 acc = ((float4*)sval)[ke * 4 + c];
    for (int j = ke + 1; j < end; j++) {
        float4 w = ((float4*)sval)[j * 4 + c];
        acc.x += w.x; acc.y += w.y; acc.z += w.z; acc.w += w.w;
    }
    bool partial = (ke == 0 && sdst[0] == d) || (end == 64 && sdst[65] == d);
    float4* op = (float4*)out + (size_t)d * 4 + c;
    if (partial) { RED4(op, acc); }
    else         { *op = acc; }
}

// dual-output variant (pass1 of each graph)
__global__ void __launch_bounds__(256) spmm_seg2(
    const float* __restrict__ za, const float* __restrict__ zb,
    const int* __restrict__ csr_a, const int* __restrict__ csr_b,
    const int* __restrict__ csr_dst,
    float* __restrict__ outa, float* __restrict__ outb, int nedges)
{
    __shared__ float sa[64 * 16];
    __shared__ float sb[64 * 16];
    __shared__ int sdst[66];
    int K0 = blockIdx.x * 64;
    int t = threadIdx.x;
    int ke = t >> 2, c = t & 3;
    int k = K0 + ke;
    if (t < 66) {
        int kk = K0 - 1 + t;
        sdst[t] = (kk >= 0 && kk < nedges) ? __ldg(csr_dst + kk) : -1;
    }
    float4 va = make_float4(0.f, 0.f, 0.f, 0.f);
    float4 vb = va;
    if (k < nedges) {
        int s1 = __ldg(csr_a + k);
        int s2 = __ldg(csr_b + k);
        va = __ldg((const float4*)za + (size_t)s1 * 4 + c);
        vb = __ldg((const float4*)zb + (size_t)s2 * 4 + c);
    }
    ((float4*)sa)[ke * 4 + c] = va;
    ((float4*)sb)[ke * 4 + c] = vb;
    __syncthreads();
    if (k >= nedges) return;
    int d = sdst[1 + ke];
    if (ke != 0 && sdst[ke] == d) return;  // not a local segment head
    int end = ke + 1;
    while (end < 64 && sdst[1 + end] == d) end++;
    float4 aa = ((float4*)sa)[ke * 4 + c];
    float4 ab = ((float4*)sb)[ke * 4 + c];
    for (int j = ke + 1; j < end; j++) {
        float4 w1 = ((float4*)sa)[j * 4 + c];
        float4 w2 = ((float4*)sb)[j * 4 + c];
        aa.x += w1.x; aa.y += w1.y; aa.z += w1.z; aa.w += w1.w;
        ab.x += w2.x; ab.y += w2.y; ab.z += w2.z; ab.w += w2.w;
    }
    bool partial = (ke == 0 && sdst[0] == d) || (end == 64 && sdst[65] == d);
    float4* opa = (float4*)outa + (size_t)d * 4 + c;
    float4* opb = (float4*)outb + (size_t)d * 4 + c;
    if (partial) { RED4(opa, aa); RED4(opb, ab); }
    else         { *opa = aa; *opb = ab; }
}

// ---------------- fused 6-way lin + relu-fold + BN stats (f32x2, 2 rows/thread) ----
__global__ void __launch_bounds__(256) fused_gemm2(
    const float* __restrict__ in0, const float* __restrict__ deg,
    const float* __restrict__ agg, const float* __restrict__ z1p,
    const float* __restrict__ z2p, const float* __restrict__ z4p,
    const float* __restrict__ W, const float* __restrict__ Bv,
    float* __restrict__ hout, int statsel, int nrows)
{
    __shared__ float ws[96 * 32];
    __shared__ unsigned long long bs2[16];
    __shared__ float redbuf[8 * 32];

    for (int t = threadIdx.x; t < 96 * 32; t += 256) {
        int kb = t >> 9;
        int rem = t & 511;
        int j = rem >> 4;
        int i = rem & 15;
        ws[(kb * 16 + i) * 32 + j] = W[t];
    }
    if (threadIdx.x < 16) {
        float lo = 0.f, hi = 0.f;
        #pragma unroll
        for (int kb = 0; kb < 6; kb++) {
            lo += Bv[kb * 32 + 2 * threadIdx.x];
            hi += Bv[kb * 32 + 2 * threadIdx.x + 1];
        }
        bs2[threadIdx.x] = pk2(lo, hi);
    }
    __syncthreads();

    int r0 = blockIdx.x * 512 + threadIdx.x;
    int r1 = r0 + 256;
    bool ok0 = r0 < nrows, ok1 = r1 < nrows;

    unsigned long long acc0[16], acc1[16];
    #pragma unroll
    for (int q = 0; q < 16; q++) { acc0[q] = bs2[q]; acc1[q] = bs2[q]; }

    float v0[16], v1[16];
    #pragma unroll
    for (int q = 0; q < 16; q++) { v0[q] = 0.f; v1[q] = 0.f; }
    float dg0 = ok0 ? __ldg(deg + r0) : 0.f;
    float dg1 = ok1 ? __ldg(deg + r1) : 0.f;

    #pragma unroll 1
    for (int kb = 0; kb < 6; kb++) {
        const float* sp = (kb <= 1) ? in0 : (kb == 2) ? agg : (kb == 3) ? z1p
                        : (kb == 4) ? z2p : z4p;
        if (ok0) {
            const float4* p = (const float4*)sp + (size_t)r0 * 4;
            float4 a = __ldg(p), b = __ldg(p + 1), c = __ldg(p + 2), d = __ldg(p + 3);
            v0[0]=a.x; v0[1]=a.y; v0[2]=a.z; v0[3]=a.w;
            v0[4]=b.x; v0[5]=b.y; v0[6]=b.z; v0[7]=b.w;
            v0[8]=c.x; v0[9]=c.y; v0[10]=c.z; v0[11]=c.w;
            v0[12]=d.x; v0[13]=d.y; v0[14]=d.z; v0[15]=d.w;
        }
        if (ok1) {
            const float4* p = (const float4*)sp + (size_t)r1 * 4;
            float4 a = __ldg(p), b = __ldg(p + 1), c = __ldg(p + 2), d = __ldg(p + 3);
            v1[0]=a.x; v1[1]=a.y; v1[2]=a.z; v1[3]=a.w;
            v1[4]=b.x; v1[5]=b.y; v1[6]=b.z; v1[7]=b.w;
            v1[8]=c.x; v1[9]=c.y; v1[10]=c.z; v1[11]=c.w;
            v1[12]=d.x; v1[13]=d.y; v1[14]=d.z; v1[15]=d.w;
        }
        if (kb == 1) {
            #pragma unroll
            for (int q = 0; q < 16; q++) { v0[q] *= dg0; v1[q] *= dg1; }
        }
        #pragma unroll
        for (int i = 0; i < 16; i++) {
            unsigned long long vd0 = pk2(v0[i], v0[i]);
            unsigned long long vd1 = pk2(v1[i], v1[i]);
            const ulonglong2* wp2 = (const ulonglong2*)&ws[(kb * 16 + i) * 32];
            #pragma unroll
            for (int q2 = 0; q2 < 8; q2++) {
                ulonglong2 ww = wp2[q2];
                acc0[2*q2]   = fma2(vd0, ww.x, acc0[2*q2]);
                acc0[2*q2+1] = fma2(vd0, ww.y, acc0[2*q2+1]);
                acc1[2*q2]   = fma2(vd1, ww.x, acc1[2*q2]);
                acc1[2*q2+1] = fma2(vd1, ww.y, acc1[2*q2+1]);
            }
        }
    }

    float hs[16], hq[16];
    #pragma unroll
    for (int c = 0; c < 16; c++) { hs[c] = 0.f; hq[c] = 0.f; }

    if (ok0) {
        float h[16];
        #pragma unroll
        for (int q = 0; q < 8; q++) {
            float a0, a1, b0, b1;
            up2(acc0[q], a0, a1);
            up2(acc0[8 + q], b0, b1);
            h[2*q]   = a0 + fmaxf(b0, 0.f);
            h[2*q+1] = a1 + fmaxf(b1, 0.f);
        }
        float4* ho = (float4*)hout + (size_t)r0 * 4;
        ho[0] = make_float4(h[0], h[1], h[2], h[3]);
        ho[1] = make_float4(h[4], h[5], h[6], h[7]);
        ho[2] = make_float4(h[8], h[9], h[10], h[11]);
        ho[3] = make_float4(h[12], h[13], h[14], h[15]);
        #pragma unroll
        for (int c = 0; c < 16; c++) { hs[c] += h[c]; hq[c] += h[c] * h[c]; }
    }
    if (ok1) {
        float h[16];
        #pragma unroll
        for (int q = 0; q < 8; q++) {
            float a0, a1, b0, b1;
            up2(acc1[q], a0, a1);
            up2(acc1[8 + q], b0, b1);
            h[2*q]   = a0 + fmaxf(b0, 0.f);
            h[2*q+1] = a1 + fmaxf(b1, 0.f);
        }
        float4* ho = (float4*)hout + (size_t)r1 * 4;
        ho[0] = make_float4(h[0], h[1], h[2], h[3]);
        ho[1] = make_float4(h[4], h[5], h[6], h[7]);
        ho[2] = make_float4(h[8], h[9], h[10], h[11]);
        ho[3] = make_float4(h[12], h[13], h[14], h[15]);
        #pragma unroll
        for (int c = 0; c < 16; c++) { hs[c] += h[c]; hq[c] += h[c] * h[c]; }
    }

    int lane = threadIdx.x & 31;
    int warp = threadIdx.x >> 5;
    #pragma unroll
    for (int c = 0; c < 16; c++) {
        float a = hs[c];
        float b = hq[c];
        #pragma unroll
        for (int o = 16; o > 0; o >>= 1) {
            a += __shfl_xor_sync(0xFFFFFFFFu, a, o);
            b += __shfl_xor_sync(0xFFFFFFFFu, b, o);
        }
        if (lane == 0) {
            redbuf[warp * 32 + c]      = a;
            redbuf[warp * 32 + 16 + c] = b;
        }
    }
    __syncthreads();
    if (threadIdx.x < 32) {
        float s = 0.f;
        #pragma unroll
        for (int w = 0; w < 8; w++) s += redbuf[w * 32 + threadIdx.x];
        atomicAdd(&g_stats[statsel * 32 + threadIdx.x], s);
    }
}

// ---------------- BN finalize + apply ----------------
__global__ void bn_finalize(
    const float* __restrict__ wx, const float* __restrict__ bx,
    const float* __restrict__ wy, const float* __restrict__ by,
    int N, int E)
{
    int t = threadIdx.x;
    if (t >= 32) return;
    int sel = t >> 4;
    int c = t & 15;
    float cnt = sel ? (float)E : (float)N;
    float m   = g_stats[sel * 32 + c] / cnt;
    float var = g_stats[sel * 32 + 16 + c] / cnt - m * m;
    const float* w = sel ? wy : wx;
    const float* b = sel ? by : bx;
    float scale = rsqrtf(var + 1e-5f) * __ldg(w + c);
    g_bn[sel * 32 + c]      = scale;
    g_bn[sel * 32 + 16 + c] = __ldg(b + c) - m * scale;
}

__global__ void __launch_bounds__(256) bn_apply(float* __restrict__ h, int nrows, int bnoff) {
    long long i = (long long)blockIdx.x * blockDim.x + threadIdx.x;  // float4 index
    long long tot = (long long)nrows * 4;
    if (i >= tot) return;
    int c = ((int)(i & 3)) * 4;
    const float* bn = g_bn + bnoff;
    float4 v = ((float4*)h)[i];
    v.x = v.x * bn[c + 0] + bn[16 + c + 0];
    v.y = v.y * bn[c + 1] + bn[16 + c + 1];
    v.z = v.z * bn[c + 2] + bn[16 + c + 2];
    v.w = v.w * bn[c + 3] + bn[16 + c + 3];
    ((float4*)h)[i] = v;
}

// ---------------- host ----------------
static void* sym_addr(const void* s) {
    void* p = nullptr;
    cudaGetSymbolAddress(&p, s);
    return p;
}

extern "C" void kernel_launch(void* const* d_in, const int* in_sizes, int n_in,
                              void* d_out, int out_size)
{
    const float* x       = (const float*)d_in[0];
    const float* y       = (const float*)d_in[1];
    const float* deg_g   = (const float*)d_in[2];
    const float* deg_lg  = (const float*)d_in[3];
    const float* theta_W = (const float*)d_in[4];
    const float* theta_b = (const float*)d_in[5];
    const float* gamma_W = (const float*)d_in[6];
    const float* gamma_b = (const float*)d_in[7];
    const float* bn_x_w  = (const float*)d_in[8];
    const float* bn_x_b  = (const float*)d_in[9];
    const float* bn_y_w  = (const float*)d_in[10];
    const float* bn_y_b  = (const float*)d_in[11];
    const int* src_g     = (const int*)d_in[12];
    const int* dst_g     = (const int*)d_in[13];
    const int* src_lg    = (const int*)d_in[14];
    const int* dst_lg    = (const int*)d_in[15];
    const int* eid2nid   = (const int*)d_in[16];

    int N  = in_sizes[0] / 16;
    int E  = in_sizes[1] / 16;
    int EL = in_sizes[14];

    float* out_x = (float*)d_out;
    float* out_y = out_x + (size_t)N * 16;

    float* ze1   = (float*)sym_addr(g_ze1);
    float* ze2   = (float*)sym_addr(g_ze2);
    float* zet   = (float*)sym_addr(g_zet);
    float* ze4   = (float*)sym_addr(g_ze4);
    float* xyagg = (float*)sym_addr(g_xyagg);
    float* zn1   = (float*)sym_addr(g_zn1);
    float* zn2   = (float*)sym_addr(g_zn2);
    float* znt   = (float*)sym_addr(g_znt);
    float* zn4   = (float*)sym_addr(g_zn4);
    float* yx    = (float*)sym_addr(g_yx);

    int* tmp_lg  = (int*)sym_addr(g_tmp_lg);
    int* off_lg  = (int*)sym_addr(g_off_lg);
    int* csr_ls  = (int*)sym_addr(g_csr_lg_src);
    int* csr_ld  = (int*)sym_addr(g_csr_lg_dst);
    int* csr_lb  = (int*)sym_addr(g_csr_lg_b);
    int* tmp_g   = (int*)sym_addr(g_tmp_g);
    int* off_g   = (int*)sym_addr(g_off_g);
    int* csr_gs  = (int*)sym_addr(g_csr_g_src);
    int* csr_gd  = (int*)sym_addr(g_csr_g_dst);
    int* csr_gb  = (int*)sym_addr(g_csr_g_b);
    int* bs_lg   = (int*)sym_addr(g_bsums_lg);
    int* bs_g    = (int*)sym_addr(g_bsums_g);
    int* zlist_lg = (int*)sym_addr(g_zlist_lg);
    int* zlist_g  = (int*)sym_addr(g_zlist_g);
    int* zcnt     = (int*)sym_addr(g_zcnt);

    // 1) zero counts + stats + zero-list counters
    zero_small<<<cdiv_u(E > N ? E : N, 256), 256>>>(E, N);

    // 2) CSR build (dst-sorted) for both graphs
    hist_k<<<cdiv_u(EL, 256), 256>>>(dst_lg, tmp_lg, EL);
    hist_k<<<cdiv_u(E, 256), 256>>>(dst_g, tmp_g, E);

    int nb_lg = cdiv_u(E, 1024);
    scan_blocks<<<nb_lg, 256>>>(tmp_lg, off_lg, bs_lg, E);
    scan_bsums<<<1, 1024>>>(bs_lg, nb_lg);
    add_offsets<<<cdiv_u(E, 256), 256>>>(off_lg, tmp_lg, bs_lg, E, EL);

    int nb_g = cdiv_u(N, 1024);
    scan_blocks<<<nb_g, 256>>>(tmp_g, off_g, bs_g, N);
    scan_bsums<<<1, 1024>>>(bs_g, nb_g);
    add_offsets<<<cdiv_u(N, 256), 256>>>(off_g, tmp_g, bs_g, N, E);

    scatter_lg_k<<<cdiv_u(EL, 256), 256>>>(src_lg, dst_lg, eid2nid, tmp_lg,
                                           csr_ls, csr_ld, csr_lb, EL);
    scatter_g_k<<<cdiv_u(E, 256), 256>>>(src_g, dst_g, tmp_g,
                                         csr_gs, csr_gd, csr_gb, E);

    // 3) zero lists (span + empty rows) and pre-zero those rows in all buffers
    build_zero_list<<<cdiv_u(E, 256), 256>>>(csr_ld, off_lg, E, EL, zlist_lg, zcnt + 0);
    build_zero_list<<<cdiv_u(N, 256), 256>>>(csr_gd, off_g, N, E, zlist_g, zcnt + 1);
    {
        long long cap_lg = (long long)(E + EL / 64 + 64) * 4;
        long long cap_g  = (long long)(N + E / 64 + 64) * 4;
        prezero5<<<cdiv_u(cap_lg, 256), 256>>>(zlist_lg, zcnt + 0, ze1, ze2, zet, ze4, xyagg);
        prezero5<<<cdiv_u(cap_g, 256), 256>>>(zlist_g, zcnt + 1, zn1, zn2, znt, zn4, yx);
    }

    // 4) line-graph chain (edge-balanced segmented SpMM)
    unsigned gl = cdiv_u(EL, 64);
    spmm_seg2<<<gl, 256>>>(y, x, csr_ls, csr_lb, csr_ld, ze1, xyagg, EL);
    spmm_seg<<<gl, 256>>>(ze1, csr_ls, csr_ld, ze2, EL);
    spmm_seg<<<gl, 256>>>(ze2, csr_ls, csr_ld, zet, EL);
    spmm_seg<<<gl, 256>>>(zet, csr_ls, csr_ld, ze4, EL);

    // 5) node-graph chain
    unsigned gg = cdiv_u(E, 64);
    spmm_seg2<<<gg, 256>>>(x, y, csr_gs, csr_gb, csr_gd, zn1, yx, E);
    spmm_seg<<<gg, 256>>>(zn1, csr_gs, csr_gd, zn2, E);
    spmm_seg<<<gg, 256>>>(zn2, csr_gs, csr_gd, znt, E);
    spmm_seg<<<gg, 256>>>(znt, csr_gs, csr_gd, zn4, E);

    // 6) fused 6-way lin + relu-fold + BN stats
    fused_gemm2<<<cdiv_u(N, 512), 256>>>(x, deg_g, yx, zn1, zn2, zn4,
                                         theta_W, theta_b, out_x, 0, N);
    fused_gemm2<<<cdiv_u(E, 512), 256>>>(y, deg_lg, xyagg, ze1, ze2, ze4,
                                         gamma_W, gamma_b, out_y, 1, E);

    // 7) BN finalize + in-place normalize
    bn_finalize<<<1, 32>>>(bn_x_w, bn_x_b, bn_y_w, bn_y_b, N, E);
    bn_apply<<<cdiv_u((long long)N * 4, 256), 256>>>(out_x, N, 0);
    bn_apply<<<cdiv_u((long long)E * 4, 256), 256>>>(out_y, E, 32);

    (void)n_in; (void)out_size;
}